// round 11
// baseline (speedup 1.0000x reference)
#include <cuda_runtime.h>
#include <cuda_bf16.h>
#include <math.h>
#include <stdint.h>

#define Bn 128
#define Tn 256
#define Ln 64
#define Sn 25
#define Hn 128
#define NT 512

#define ZF_SZ  52428800   // 25*128*256*64
#define M_SZ   2097152    // 128*256*64

#define ZW 36    // uint32 words per z row (64 bf16 = 32 words + 4 pad)
#define TW 68    // uint32 words per th row (128 bf16 = 64 words + 4 pad)

__device__ __forceinline__ float tanh_fast(float x) {
    float y;
    asm("tanh.approx.f32 %0, %1;" : "=f"(y) : "f"(x));
    return y;
}
__device__ __forceinline__ uint32_t pack_bf(float a, float b) {
    uint16_t ua = __bfloat16_as_ushort(__float2bfloat16(a));
    uint16_t ub = __bfloat16_as_ushort(__float2bfloat16(b));
    return (uint32_t)ua | ((uint32_t)ub << 16);
}
// split two floats into packed bf16 hi-pair and lo-pair (residuals)
__device__ __forceinline__ void split2(float a, float b, uint32_t& hi, uint32_t& lo) {
    float ah = __bfloat162float(__float2bfloat16(a));
    float bh = __bfloat162float(__float2bfloat16(b));
    hi = pack_bf(a, b);
    lo = pack_bf(a - ah, b - bh);
}
__device__ __forceinline__ float2 unpk(uint32_t w) {
    float lo = __bfloat162float(__ushort_as_bfloat16((uint16_t)(w & 0xffffu)));
    float hi = __bfloat162float(__ushort_as_bfloat16((uint16_t)(w >> 16)));
    return make_float2(lo, hi);
}
__device__ __forceinline__ void mma16816(float* d, const uint32_t* a,
                                         uint32_t b0, uint32_t b1) {
    asm volatile(
        "mma.sync.aligned.m16n8k16.row.col.f32.bf16.bf16.f32 "
        "{%0,%1,%2,%3},{%4,%5,%6,%7},{%8,%9},{%0,%1,%2,%3};"
        : "+f"(d[0]), "+f"(d[1]), "+f"(d[2]), "+f"(d[3])
        : "r"(a[0]), "r"(a[1]), "r"(a[2]), "r"(a[3]), "r"(b0), "r"(b1));
}

__global__ __launch_bounds__(NT, 1)
void nlf_kernel(const float* __restrict__ k_in,
                const float* __restrict__ K_in,
                const float* __restrict__ noise,
                const float* __restrict__ logQ,
                const float* __restrict__ m0,
                const float* __restrict__ logQ0,
                const float* __restrict__ W1,
                const float* __restrict__ b1,
                const float* __restrict__ W2,
                const float* __restrict__ b2,
                float* __restrict__ out)
{
    __shared__ uint32_t zhiW[32*ZW], zloW[32*ZW];
    __shared__ uint32_t thhiW[32*TW], thloW[32*TW];
    __shared__ float sP1[128], sP2[128];

    const int tid  = threadIdx.x;
    const int b    = blockIdx.x;
    const int w    = tid >> 5;
    const int lane = tid & 31;
    const int lq   = tid & 63;

    const int mt = w & 1;        // m-tile (s-half: rows mt*16 .. mt*16+15)
    const int wn = w >> 1;       // 0..7
    const int c  = lane & 3;     // fragment col-pair / k-pair index
    const int hq = lane >> 2;    // fragment row / n index

    // -------- register-resident weight B-fragments (bf16 hi/lo) --------
    uint32_t w1h[2][4][2], w1l[2][4][2];
    #pragma unroll
    for (int j = 0; j < 2; j++) {
        int h = 8*(2*wn + j) + hq;
        #pragma unroll
        for (int ko = 0; ko < 4; ko++) {
            int k0 = 16*ko + 2*c;
            split2(W1[(k0+0)*Hn + h], W1[(k0+1)*Hn + h], w1h[j][ko][0], w1l[j][ko][0]);
            split2(W1[(k0+8)*Hn + h], W1[(k0+9)*Hn + h], w1h[j][ko][1], w1l[j][ko][1]);
        }
    }
    uint32_t w2h[8][2], w2l[8][2];
    {
        int l2 = 8*wn + hq;
        #pragma unroll
        for (int ko = 0; ko < 8; ko++) {
            int k0 = 16*ko + 2*c;
            split2(W2[(k0+0)*Ln + l2], W2[(k0+1)*Ln + l2], w2h[ko][0], w2l[ko][0]);
            split2(W2[(k0+8)*Ln + l2], W2[(k0+9)*Ln + l2], w2h[ko][1], w2l[ko][1]);
        }
    }
    // biases for D-fragment init
    float b1f[2][2];
    #pragma unroll
    for (int j = 0; j < 2; j++) {
        b1f[j][0] = b1[8*(2*wn + j) + 2*c];
        b1f[j][1] = b1[8*(2*wn + j) + 2*c + 1];
    }
    const float b2f0 = b2[8*wn + 2*c];
    const float b2f1 = b2[8*wn + 2*c + 1];
    const float Qd   = log1pf(expf(logQ[lq]));

    __nv_bfloat16* zh = (__nv_bfloat16*)zhiW;   // row stride 72 bf16
    __nv_bfloat16* zl = (__nv_bfloat16*)zloW;

    // -------- init: zero z arrays, t=0 filter --------
    for (int i = tid; i < 32*ZW; i += NT) { zhiW[i] = 0; zloW[i] = 0; }
    if (tid < 64) {
        int l = tid;
        float P0 = log1pf(expf(logQ0[l]));
        float J0 = 1.0f / P0;
        float h0 = J0 * m0[l];
        int  go  = (b*Tn + 0)*Ln + l;
        float Kv = K_in[go], kv = k_in[go];
        float Jf = J0 + Kv;
        float Pf = 1.0f / Jf;
        float mf = Pf * (h0 + kv);
        out[ZF_SZ + 0*M_SZ + go] = mf;
        out[ZF_SZ + 1*M_SZ + go] = m0[l];
        out[ZF_SZ + 2*M_SZ + go] = Pf;
        out[ZF_SZ + 3*M_SZ + go] = P0;
        sP1[l] = mf;
        sP2[l] = sqrtf(Pf);
    }
    __syncthreads();

    // z update for t = 0
    {
        float mf = sP1[lq], spf = sP2[lq];
        #pragma unroll
        for (int i = 0; i < 3; i++) {
            int idx = tid + i*NT, s = idx >> 6;
            float zv = mf + spf * noise[((0*Sn + s)*Bn + b)*Ln + lq];
            out[((s*Bn + b)*Tn + 0)*Ln + lq] = zv;
            float zvh = __bfloat162float(__float2bfloat16(zv));
            zh[s*72 + lq] = __float2bfloat16(zv);
            zl[s*72 + lq] = __float2bfloat16(zv - zvh);
        }
        if (tid < 64) {
            float zv = mf + spf * noise[((0*Sn + 24)*Bn + b)*Ln + lq];
            out[((24*Bn + b)*Tn + 0)*Ln + lq] = zv;
            float zvh = __bfloat162float(__float2bfloat16(zv));
            zh[24*72 + lq] = __float2bfloat16(zv);
            zl[24*72 + lq] = __float2bfloat16(zv - zvh);
        }
    }

    const int rowA = mt*16 + hq;   // A-fragment base row (s)

    for (int t = 1; t < Tn; t++) {
        // -------- prefetch globals --------
        float npf[4];
        #pragma unroll
        for (int i = 0; i < 3; i++) {
            int idx = tid + i*NT;
            npf[i] = noise[((t*Sn + (idx >> 6))*Bn + b)*Ln + lq];
        }
        npf[3] = (tid < 64) ? noise[((t*Sn + 24)*Bn + b)*Ln + lq] : 0.0f;
        const int go = (b*Tn + t)*Ln + lq;
        const float Kv_pf = K_in[go];
        const float kv_pf = k_in[go];

        __syncthreads();   // z for this step ready

        // ============ GEMM1: th = tanh(z @ W1 + b1) via HMMA ============
        {
            float d[2][4];
            #pragma unroll
            for (int j = 0; j < 2; j++) {
                d[j][0] = b1f[j][0]; d[j][1] = b1f[j][1];
                d[j][2] = b1f[j][0]; d[j][3] = b1f[j][1];
            }
            #pragma unroll
            for (int ko = 0; ko < 4; ko++) {
                uint32_t ah[4], al[4];
                int base = rowA*ZW + 8*ko + c;
                ah[0] = zhiW[base];          ah[1] = zhiW[base + 8*ZW];
                ah[2] = zhiW[base + 4];      ah[3] = zhiW[base + 8*ZW + 4];
                al[0] = zloW[base];          al[1] = zloW[base + 8*ZW];
                al[2] = zloW[base + 4];      al[3] = zloW[base + 8*ZW + 4];
                #pragma unroll
                for (int j = 0; j < 2; j++) {
                    mma16816(d[j], ah, w1h[j][ko][0], w1h[j][ko][1]);
                    mma16816(d[j], al, w1h[j][ko][0], w1h[j][ko][1]);
                    mma16816(d[j], ah, w1l[j][ko][0], w1l[j][ko][1]);
                }
            }
            #pragma unroll
            for (int j = 0; j < 2; j++) {
                int nj = 2*wn + j;
                float t0 = tanh_fast(d[j][0]), t1 = tanh_fast(d[j][1]);
                float t2 = tanh_fast(d[j][2]), t3 = tanh_fast(d[j][3]);
                uint32_t h01, l01, h23, l23;
                split2(t0, t1, h01, l01);
                split2(t2, t3, h23, l23);
                int r0 = rowA*TW + 4*nj + c;
                thhiW[r0] = h01;           thloW[r0] = l01;
                thhiW[r0 + 8*TW] = h23;    thloW[r0 + 8*TW] = l23;
            }
        }
        __syncthreads();

        // ============ GEMM2: m_th = z + th @ W2 + b2, fused moments ============
        {
            float e[4];
            e[0] = b2f0; e[1] = b2f1; e[2] = b2f0; e[3] = b2f1;
            #pragma unroll
            for (int ko = 0; ko < 8; ko++) {
                uint32_t ah[4], al[4];
                int base = rowA*TW + 8*ko + c;
                ah[0] = thhiW[base];         ah[1] = thhiW[base + 8*TW];
                ah[2] = thhiW[base + 4];     ah[3] = thhiW[base + 8*TW + 4];
                al[0] = thloW[base];         al[1] = thloW[base + 8*TW];
                al[2] = thloW[base + 4];     al[3] = thloW[base + 8*TW + 4];
                mma16816(e, ah, w2h[ko][0], w2h[ko][1]);
                mma16816(e, al, w2h[ko][0], w2h[ko][1]);
                mma16816(e, ah, w2l[ko][0], w2l[ko][1]);
            }
            // add z back (bf16 hi+lo reconstruction)
            int zb = rowA*ZW + 4*wn + c;
            float2 z0h = unpk(zhiW[zb]),        z0l = unpk(zloW[zb]);
            float2 z1h = unpk(zhiW[zb + 8*ZW]), z1l = unpk(zloW[zb + 8*ZW]);
            float m0v = e[0] + z0h.x + z0l.x;
            float m1v = e[1] + z0h.y + z0l.y;
            float m2v = e[2] + z1h.x + z1l.x;
            float m3v = e[3] + z1h.y + z1l.y;
            // mask samples s >= 25 (only rows 24+hq with hq>0, mt==1)
            if (mt == 1 && hq > 0) { m2v = 0.0f; m3v = 0.0f; }
            float p0 = m0v + m2v, p1 = m1v + m3v;
            float q0 = m0v*m0v + m2v*m2v, q1 = m1v*m1v + m3v*m3v;
            #pragma unroll
            for (int msk = 4; msk <= 16; msk <<= 1) {
                p0 += __shfl_xor_sync(0xffffffffu, p0, msk);
                p1 += __shfl_xor_sync(0xffffffffu, p1, msk);
                q0 += __shfl_xor_sync(0xffffffffu, q0, msk);
                q1 += __shfl_xor_sync(0xffffffffu, q1, msk);
            }
            if (hq == 0) {
                int li = mt*64 + 8*wn + 2*c;
                sP1[li] = p0; sP1[li+1] = p1;
                sP2[li] = q0; sP2[li+1] = q1;
            }
        }
        __syncthreads();

        // -------- filter update (all threads, redundant per l) --------
        float s1 = sP1[lq] + sP1[64 + lq];
        float s2 = sP2[lq] + sP2[64 + lq];
        float mp = s1 * (1.0f/25.0f);
        float Pp = Qd + s2 * (1.0f/25.0f) - mp*mp;
        float Jp = 1.0f / Pp;
        float Jf = Jp + Kv_pf;
        float Pf = 1.0f / Jf;
        float mf = Pf * (Jp*mp + kv_pf);
        float spf = sqrtf(Pf);
        if (tid < 64) {
            out[ZF_SZ + 0*M_SZ + go] = mf;
            out[ZF_SZ + 1*M_SZ + go] = mp;
            out[ZF_SZ + 2*M_SZ + go] = Pf;
            out[ZF_SZ + 3*M_SZ + go] = Pp;
        }

        // -------- z update + z_f output --------
        #pragma unroll
        for (int i = 0; i < 3; i++) {
            int idx = tid + i*NT, s = idx >> 6;
            float zv = mf + spf * npf[i];
            out[((s*Bn + b)*Tn + t)*Ln + lq] = zv;
            float zvh = __bfloat162float(__float2bfloat16(zv));
            zh[s*72 + lq] = __float2bfloat16(zv);
            zl[s*72 + lq] = __float2bfloat16(zv - zvh);
        }
        if (tid < 64) {
            float zv = mf + spf * npf[3];
            out[((24*Bn + b)*Tn + t)*Ln + lq] = zv;
            float zvh = __bfloat162float(__float2bfloat16(zv));
            zh[24*72 + lq] = __float2bfloat16(zv);
            zl[24*72 + lq] = __float2bfloat16(zv - zvh);
        }
    }
}

extern "C" void kernel_launch(void* const* d_in, const int* in_sizes, int n_in,
                              void* d_out, int out_size)
{
    const float* k_in  = (const float*)d_in[0];
    const float* K_in  = (const float*)d_in[1];
    const float* noise = (const float*)d_in[2];
    const float* logQ  = (const float*)d_in[3];
    const float* m0    = (const float*)d_in[4];
    const float* logQ0 = (const float*)d_in[5];
    const float* W1    = (const float*)d_in[6];
    const float* b1    = (const float*)d_in[7];
    const float* W2    = (const float*)d_in[8];
    const float* b2    = (const float*)d_in[9];
    float* out = (float*)d_out;

    nlf_kernel<<<Bn, NT>>>(k_in, K_in, noise, logQ, m0, logQ0,
                           W1, b1, W2, b2, out);
}

// round 12
// speedup vs baseline: 1.0464x; 1.0464x over previous
#include <cuda_runtime.h>
#include <cuda_bf16.h>
#include <math.h>
#include <stdint.h>

#define Bn 128
#define Tn 256
#define Ln 64
#define Sn 25
#define Hn 128
#define NT 512

#define ZF_SZ  52428800   // 25*128*256*64
#define M_SZ   2097152    // 128*256*64

#define ZW 36    // uint32 words per z row (64 bf16 = 32 words + 4 pad)
#define TW 68    // uint32 words per th row (128 bf16 = 64 words + 4 pad)

__device__ __forceinline__ float tanh_fast(float x) {
    float y;
    asm("tanh.approx.f32 %0, %1;" : "=f"(y) : "f"(x));
    return y;
}
__device__ __forceinline__ uint32_t pack_bf(float a, float b) {
    uint16_t ua = __bfloat16_as_ushort(__float2bfloat16(a));
    uint16_t ub = __bfloat16_as_ushort(__float2bfloat16(b));
    return (uint32_t)ua | ((uint32_t)ub << 16);
}
__device__ __forceinline__ void split2(float a, float b, uint32_t& hi, uint32_t& lo) {
    float ah = __bfloat162float(__float2bfloat16(a));
    float bh = __bfloat162float(__float2bfloat16(b));
    hi = pack_bf(a, b);
    lo = pack_bf(a - ah, b - bh);
}
__device__ __forceinline__ float2 unpk(uint32_t w) {
    float lo = __bfloat162float(__ushort_as_bfloat16((uint16_t)(w & 0xffffu)));
    float hi = __bfloat162float(__ushort_as_bfloat16((uint16_t)(w >> 16)));
    return make_float2(lo, hi);
}
__device__ __forceinline__ void mma16816(float* d, const uint32_t* a,
                                         uint32_t b0, uint32_t b1) {
    asm volatile(
        "mma.sync.aligned.m16n8k16.row.col.f32.bf16.bf16.f32 "
        "{%0,%1,%2,%3},{%4,%5,%6,%7},{%8,%9},{%0,%1,%2,%3};"
        : "+f"(d[0]), "+f"(d[1]), "+f"(d[2]), "+f"(d[3])
        : "r"(a[0]), "r"(a[1]), "r"(a[2]), "r"(a[3]), "r"(b0), "r"(b1));
}
__device__ __forceinline__ void ldm4(uint32_t addr, uint32_t* r) {
    asm volatile("ldmatrix.sync.aligned.m8n8.x4.shared.b16 {%0,%1,%2,%3}, [%4];"
        : "=r"(r[0]), "=r"(r[1]), "=r"(r[2]), "=r"(r[3]) : "r"(addr));
}

__global__ __launch_bounds__(NT, 1)
void nlf_kernel(const float* __restrict__ k_in,
                const float* __restrict__ K_in,
                const float* __restrict__ noise,
                const float* __restrict__ logQ,
                const float* __restrict__ m0,
                const float* __restrict__ logQ0,
                const float* __restrict__ W1,
                const float* __restrict__ b1,
                const float* __restrict__ W2,
                const float* __restrict__ b2,
                float* __restrict__ out)
{
    __shared__ uint32_t zhiW[32*ZW], zloW[32*ZW];
    __shared__ uint32_t thhiW[32*TW], thloW[32*TW];
    __shared__ float sP1[128], sP2[128];

    const int tid  = threadIdx.x;
    const int b    = blockIdx.x;
    const int w    = tid >> 5;
    const int lane = tid & 31;
    const int lq   = tid & 63;

    const int mt = w & 1;        // m-tile (s-half)
    const int wn = w >> 1;       // 0..7
    const int c  = lane & 3;     // fragment k-pair index
    const int hq = lane >> 2;    // fragment row index

    // ldmatrix per-lane addresses (row = mt*16 + lane&15, colw = (lane>>4)*4)
    const int lrow = mt*16 + (lane & 15);
    const int lcw  = (lane >> 4) * 4;
    const uint32_t zhB  = (uint32_t)__cvta_generic_to_shared(zhiW)  + (lrow*ZW + lcw)*4;
    const uint32_t zlB  = (uint32_t)__cvta_generic_to_shared(zloW)  + (lrow*ZW + lcw)*4;
    const uint32_t thB  = (uint32_t)__cvta_generic_to_shared(thhiW) + (lrow*TW + lcw)*4;
    const uint32_t tlB  = (uint32_t)__cvta_generic_to_shared(thloW) + (lrow*TW + lcw)*4;

    // -------- register-resident weight B-fragments (bf16 hi/lo) --------
    uint32_t w1h[2][4][2], w1l[2][4][2];
    #pragma unroll
    for (int j = 0; j < 2; j++) {
        int h = 8*(2*wn + j) + hq;
        #pragma unroll
        for (int ko = 0; ko < 4; ko++) {
            int k0 = 16*ko + 2*c;
            split2(W1[(k0+0)*Hn + h], W1[(k0+1)*Hn + h], w1h[j][ko][0], w1l[j][ko][0]);
            split2(W1[(k0+8)*Hn + h], W1[(k0+9)*Hn + h], w1h[j][ko][1], w1l[j][ko][1]);
        }
    }
    uint32_t w2h[8][2], w2l[8][2];
    {
        int l2 = 8*wn + hq;
        #pragma unroll
        for (int ko = 0; ko < 8; ko++) {
            int k0 = 16*ko + 2*c;
            split2(W2[(k0+0)*Ln + l2], W2[(k0+1)*Ln + l2], w2h[ko][0], w2l[ko][0]);
            split2(W2[(k0+8)*Ln + l2], W2[(k0+9)*Ln + l2], w2h[ko][1], w2l[ko][1]);
        }
    }
    float b1f[2][2];
    #pragma unroll
    for (int j = 0; j < 2; j++) {
        b1f[j][0] = b1[8*(2*wn + j) + 2*c];
        b1f[j][1] = b1[8*(2*wn + j) + 2*c + 1];
    }
    const float b2f0 = b2[8*wn + 2*c];
    const float b2f1 = b2[8*wn + 2*c + 1];
    const float Qd   = log1pf(expf(logQ[lq]));

    __nv_bfloat16* zh = (__nv_bfloat16*)zhiW;   // row stride 72 bf16
    __nv_bfloat16* zl = (__nv_bfloat16*)zloW;

    // -------- init: zero z arrays, t=0 filter --------
    for (int i = tid; i < 32*ZW; i += NT) { zhiW[i] = 0; zloW[i] = 0; }
    if (tid < 64) {
        int l = tid;
        float P0 = log1pf(expf(logQ0[l]));
        float J0 = 1.0f / P0;
        float h0 = J0 * m0[l];
        int  go  = (b*Tn + 0)*Ln + l;
        float Kv = K_in[go], kv = k_in[go];
        float Jf = J0 + Kv;
        float Pf = 1.0f / Jf;
        float mf = Pf * (h0 + kv);
        out[ZF_SZ + 0*M_SZ + go] = mf;
        out[ZF_SZ + 1*M_SZ + go] = m0[l];
        out[ZF_SZ + 2*M_SZ + go] = Pf;
        out[ZF_SZ + 3*M_SZ + go] = P0;
        sP1[l] = mf;
        sP2[l] = sqrtf(Pf);
    }
    __syncthreads();

    // z update for t = 0
    {
        float mf = sP1[lq], spf = sP2[lq];
        #pragma unroll
        for (int i = 0; i < 3; i++) {
            int idx = tid + i*NT, s = idx >> 6;
            float zv = mf + spf * noise[((0*Sn + s)*Bn + b)*Ln + lq];
            out[((s*Bn + b)*Tn + 0)*Ln + lq] = zv;
            float zvh = __bfloat162float(__float2bfloat16(zv));
            zh[s*72 + lq] = __float2bfloat16(zv);
            zl[s*72 + lq] = __float2bfloat16(zv - zvh);
        }
        if (tid < 64) {
            float zv = mf + spf * noise[((0*Sn + 24)*Bn + b)*Ln + lq];
            out[((24*Bn + b)*Tn + 0)*Ln + lq] = zv;
            float zvh = __bfloat162float(__float2bfloat16(zv));
            zh[24*72 + lq] = __float2bfloat16(zv);
            zl[24*72 + lq] = __float2bfloat16(zv - zvh);
        }
    }

    const int rowA = mt*16 + hq;
    const bool storeHi = (mt == 0) || (hq == 0);   // row rowA+8 < 25

    for (int t = 1; t < Tn; t++) {
        // -------- prefetch globals --------
        float npf[4];
        #pragma unroll
        for (int i = 0; i < 3; i++) {
            int idx = tid + i*NT;
            npf[i] = noise[((t*Sn + (idx >> 6))*Bn + b)*Ln + lq];
        }
        npf[3] = (tid < 64) ? noise[((t*Sn + 24)*Bn + b)*Ln + lq] : 0.0f;
        const int go = (b*Tn + t)*Ln + lq;
        const float Kv_pf = K_in[go];
        const float kv_pf = k_in[go];

        __syncthreads();   // z for this step ready

        // ============ GEMM1: th = tanh(z @ W1 + b1), split-chain HMMA ============
        {
            float dH[2][4], dX[2][4];
            #pragma unroll
            for (int j = 0; j < 2; j++) {
                dH[j][0] = b1f[j][0]; dH[j][1] = b1f[j][1];
                dH[j][2] = b1f[j][0]; dH[j][3] = b1f[j][1];
                dX[j][0] = 0.0f; dX[j][1] = 0.0f; dX[j][2] = 0.0f; dX[j][3] = 0.0f;
            }
            #pragma unroll
            for (int ko = 0; ko < 4; ko++) {
                uint32_t ah[4], al[4];
                ldm4(zhB + 32*ko, ah);
                ldm4(zlB + 32*ko, al);
                #pragma unroll
                for (int j = 0; j < 2; j++) {
                    mma16816(dH[j], ah, w1h[j][ko][0], w1h[j][ko][1]);
                    mma16816(dX[j], al, w1h[j][ko][0], w1h[j][ko][1]);
                    mma16816(dX[j], ah, w1l[j][ko][0], w1l[j][ko][1]);
                }
            }
            #pragma unroll
            for (int j = 0; j < 2; j++) {
                int nj = 2*wn + j;
                int r0 = rowA*TW + 4*nj + c;
                float t0 = tanh_fast(dH[j][0] + dX[j][0]);
                float t1 = tanh_fast(dH[j][1] + dX[j][1]);
                uint32_t h01, l01;
                split2(t0, t1, h01, l01);
                thhiW[r0] = h01;  thloW[r0] = l01;
                if (storeHi) {
                    float t2 = tanh_fast(dH[j][2] + dX[j][2]);
                    float t3 = tanh_fast(dH[j][3] + dX[j][3]);
                    uint32_t h23, l23;
                    split2(t2, t3, h23, l23);
                    thhiW[r0 + 8*TW] = h23;  thloW[r0 + 8*TW] = l23;
                }
            }
        }
        __syncthreads();

        // ============ GEMM2: m_th = z + th @ W2 + b2, fused moments ============
        {
            float eH[4], eX[4];
            eH[0] = b2f0; eH[1] = b2f1; eH[2] = b2f0; eH[3] = b2f1;
            eX[0] = 0.0f; eX[1] = 0.0f; eX[2] = 0.0f; eX[3] = 0.0f;
            #pragma unroll
            for (int ko = 0; ko < 8; ko++) {
                uint32_t ah[4], al[4];
                ldm4(thB + 32*ko, ah);
                ldm4(tlB + 32*ko, al);
                mma16816(eH, ah, w2h[ko][0], w2h[ko][1]);
                mma16816(eX, al, w2h[ko][0], w2h[ko][1]);
                mma16816(eX, ah, w2l[ko][0], w2l[ko][1]);
            }
            int zb = rowA*ZW + 4*wn + c;
            float2 z0h = unpk(zhiW[zb]),        z0l = unpk(zloW[zb]);
            float2 z1h = unpk(zhiW[zb + 8*ZW]), z1l = unpk(zloW[zb + 8*ZW]);
            float m0v = eH[0] + eX[0] + z0h.x + z0l.x;
            float m1v = eH[1] + eX[1] + z0h.y + z0l.y;
            float m2v = eH[2] + eX[2] + z1h.x + z1l.x;
            float m3v = eH[3] + eX[3] + z1h.y + z1l.y;
            if (mt == 1 && hq > 0) { m2v = 0.0f; m3v = 0.0f; }   // rows >= 25
            float p0 = m0v + m2v, p1 = m1v + m3v;
            float q0 = m0v*m0v + m2v*m2v, q1 = m1v*m1v + m3v*m3v;
            #pragma unroll
            for (int msk = 4; msk <= 16; msk <<= 1) {
                p0 += __shfl_xor_sync(0xffffffffu, p0, msk);
                p1 += __shfl_xor_sync(0xffffffffu, p1, msk);
                q0 += __shfl_xor_sync(0xffffffffu, q0, msk);
                q1 += __shfl_xor_sync(0xffffffffu, q1, msk);
            }
            if (hq == 0) {
                int li = mt*64 + 8*wn + 2*c;
                sP1[li] = p0; sP1[li+1] = p1;
                sP2[li] = q0; sP2[li+1] = q1;
            }
        }
        __syncthreads();

        // -------- filter update (all threads, redundant per l) --------
        float s1 = sP1[lq] + sP1[64 + lq];
        float s2 = sP2[lq] + sP2[64 + lq];
        float mp = s1 * (1.0f/25.0f);
        float Pp = Qd + s2 * (1.0f/25.0f) - mp*mp;
        float Jp = 1.0f / Pp;
        float Jf = Jp + Kv_pf;
        float Pf = 1.0f / Jf;
        float mf = Pf * (Jp*mp + kv_pf);
        float spf = sqrtf(Pf);
        if (tid < 64) {
            out[ZF_SZ + 0*M_SZ + go] = mf;
            out[ZF_SZ + 1*M_SZ + go] = mp;
            out[ZF_SZ + 2*M_SZ + go] = Pf;
            out[ZF_SZ + 3*M_SZ + go] = Pp;
        }

        // -------- z update + z_f output --------
        #pragma unroll
        for (int i = 0; i < 3; i++) {
            int idx = tid + i*NT, s = idx >> 6;
            float zv = mf + spf * npf[i];
            out[((s*Bn + b)*Tn + t)*Ln + lq] = zv;
            float zvh = __bfloat162float(__float2bfloat16(zv));
            zh[s*72 + lq] = __float2bfloat16(zv);
            zl[s*72 + lq] = __float2bfloat16(zv - zvh);
        }
        if (tid < 64) {
            float zv = mf + spf * npf[3];
            out[((24*Bn + b)*Tn + t)*Ln + lq] = zv;
            float zvh = __bfloat162float(__float2bfloat16(zv));
            zh[24*72 + lq] = __float2bfloat16(zv);
            zl[24*72 + lq] = __float2bfloat16(zv - zvh);
        }
    }
}

extern "C" void kernel_launch(void* const* d_in, const int* in_sizes, int n_in,
                              void* d_out, int out_size)
{
    const float* k_in  = (const float*)d_in[0];
    const float* K_in  = (const float*)d_in[1];
    const float* noise = (const float*)d_in[2];
    const float* logQ  = (const float*)d_in[3];
    const float* m0    = (const float*)d_in[4];
    const float* logQ0 = (const float*)d_in[5];
    const float* W1    = (const float*)d_in[6];
    const float* b1    = (const float*)d_in[7];
    const float* W2    = (const float*)d_in[8];
    const float* b2    = (const float*)d_in[9];
    float* out = (float*)d_out;

    nlf_kernel<<<Bn, NT>>>(k_in, K_in, noise, logQ, m0, logQ0,
                           W1, b1, W2, b2, out);
}